// round 3
// baseline (speedup 1.0000x reference)
#include <cuda_runtime.h>
#include <cuda_bf16.h>
#include <cstdint>

// SpatialAttentionLayer_23381801959766
//
// Reference math:
//   attn = softmax(fourier_maps(sensor_locs) @ W, axis=-1)   # rows sum to 1
//   out  = einsum('si,sjk->sjk', attn, X)                    # i summed out
//        = X * (row-sum of softmax) = X  (to fp32 ULP)
//
// The layer is the identity on X. Target: HBM streaming-copy roofline,
// 2 x 142.6 MB. R2: float4 + .cs, MLP=4 -> 6.1 TB/s (77% DRAM).
// R3: MLP=8 front-batched loads per thread to deepen per-warp outstanding
// load queue (M_max ~55/warp on B300; we were at 4).

static constexpr int THREADS = 256;
static constexpr int VEC_PER_THREAD = 8;   // 8 x float4 = 128 B per thread

__global__ __launch_bounds__(THREADS)
void stream_copy_kernel(const float4* __restrict__ in,
                        float4* __restrict__ out) {
    size_t base = (size_t)blockIdx.x * (THREADS * VEC_PER_THREAD) + threadIdx.x;

    float4 v[VEC_PER_THREAD];
    // Front-batch all loads (MLP=8 per thread), then all stores.
    #pragma unroll
    for (int i = 0; i < VEC_PER_THREAD; i++)
        v[i] = __ldcs(in + base + (size_t)i * THREADS);
    #pragma unroll
    for (int i = 0; i < VEC_PER_THREAD; i++)
        __stcs(out + base + (size_t)i * THREADS, v[i]);
}

// Tail kernel for any remainder (not needed for this exact shape).
__global__ void stream_copy_tail(const float* __restrict__ in,
                                 float* __restrict__ out,
                                 size_t start, size_t n) {
    size_t i = start + blockIdx.x * (size_t)blockDim.x + threadIdx.x;
    if (i < n) out[i] = __ldcs(in + i);
}

extern "C" void kernel_launch(void* const* d_in, const int* in_sizes, int n_in,
                              void* d_out, int out_size) {
    const float* X = (const float*)d_in[0];
    float* out = (float*)d_out;

    size_t n = (size_t)out_size;                          // 35,651,584 floats
    size_t n4 = n / 4;                                    // 8,912,896 float4
    size_t per_block = (size_t)THREADS * VEC_PER_THREAD;  // 2048 float4/block
    size_t full_blocks = n4 / per_block;                  // 4352 exact here

    if (full_blocks > 0) {
        stream_copy_kernel<<<(unsigned)full_blocks, THREADS>>>(
            (const float4*)X, (float4*)out);
    }
    size_t done = full_blocks * per_block * 4;            // floats covered
    if (done < n) {
        size_t rem = n - done;
        unsigned tb = (unsigned)((rem + 255) / 256);
        stream_copy_tail<<<tb, 256>>>(X, out, done, n);
    }
}